// round 13
// baseline (speedup 1.0000x reference)
#include <cuda_runtime.h>
#include <cuda_bf16.h>
#include <math.h>

typedef __nv_bfloat16 bf;

#define BB 64
#define TT 512
#define II 256
#define HH 512
#define CC 128

#define NBLK 128
#define NTHR 256
#define NWAVE (TT + 1)   // 513

#define K0 768
#define K1 1024
#define NCH0 12
#define NCH1 16

// smem: 3 chunk buffers, each: Whi 8K | Wlo 8K | Xhi 4K | Xlo 4K = 24KB
#define BUFB 24576
#define SM_EX (3 * BUFB)
#define EXPITCH 34
#define SMEM_TOTAL (SM_EX + 4 * 64 * EXPITCH * 4)   // 108544

#define SWZ(o) ((o) ^ (((o) >> 3) & 0x70))

// ---------------- device scratch ----------------
__device__ __align__(256) bf g_w0h[2048 * K0], g_w0l[2048 * K0];
__device__ __align__(256) bf g_w1h[2048 * K1], g_w1l[2048 * K1];
__device__ __align__(256) bf g_xh[(size_t)BB * TT * II], g_xl[(size_t)BB * TT * II];
__device__ __align__(256) bf g_h0h[2][BB * HH], g_h0l[2][BB * HH];
__device__ __align__(256) bf g_h1h[2][BB * HH], g_h1l[2][BB * HH];
__device__ float g_h1last[BB * HH];
__device__ unsigned g_ctr;   // zero-init; self-resets

// ---------------- primitives ----------------
__device__ __forceinline__ void cp16(unsigned saddr, const void* g) {
    asm volatile("cp.async.cg.shared.global [%0], [%1], 16;\n" :: "r"(saddr), "l"(g) : "memory");
}
__device__ __forceinline__ void cp_commit() {
    asm volatile("cp.async.commit_group;\n" ::: "memory");
}
template <int N> __device__ __forceinline__ void cp_wait() {
    asm volatile("cp.async.wait_group %0;\n" :: "n"(N) : "memory");
}
__device__ __forceinline__ void bar_arrive(unsigned* ctr, unsigned finalv) {
    unsigned old;
    asm volatile("atom.release.gpu.global.add.u32 %0, [%1], %2;"
                 : "=r"(old) : "l"(ctr), "r"(1u) : "memory");
    if (old == finalv - 1u)
        asm volatile("st.relaxed.gpu.global.u32 [%0], %1;" :: "l"(ctr), "r"(0u) : "memory");
}
__device__ __forceinline__ void bar_wait(unsigned* ctr, unsigned target) {
    unsigned v;
    do {
        asm volatile("ld.acquire.gpu.global.u32 %0, [%1];" : "=r"(v) : "l"(ctr) : "memory");
    } while (v < target);
}
__device__ __forceinline__ float sig_(float x)  { return 1.0f / (1.0f + __expf(-x)); }
__device__ __forceinline__ float tanh_(float x) { return 2.0f / (1.0f + __expf(-2.0f * x)) - 1.0f; }

__device__ __forceinline__ void ldsm4(unsigned* r, unsigned addr) {
    asm volatile("ldmatrix.sync.aligned.m8n8.x4.shared.b16 {%0,%1,%2,%3}, [%4];"
                 : "=r"(r[0]), "=r"(r[1]), "=r"(r[2]), "=r"(r[3]) : "r"(addr));
}
__device__ __forceinline__ void mma16816(float* c, const unsigned* a, unsigned b0, unsigned b1) {
    asm volatile(
        "mma.sync.aligned.m16n8k16.row.col.f32.bf16.bf16.f32 "
        "{%0,%1,%2,%3}, {%4,%5,%6,%7}, {%8,%9}, {%0,%1,%2,%3};"
        : "+f"(c[0]), "+f"(c[1]), "+f"(c[2]), "+f"(c[3])
        : "r"(a[0]), "r"(a[1]), "r"(a[2]), "r"(a[3]), "r"(b0), "r"(b1));
}

// ---------------- staging: one K=64 chunk (W 64x64 + X 32x64, hi+lo planes) ----------
__device__ __forceinline__ void stage(
    unsigned sbase, unsigned bufoff, int ch, int layer, int sub, int nb, int step, int tid, int K,
    const bf* __restrict__ wh, const bf* __restrict__ wl,
    const bf* h0h_, const bf* h0l_, const bf* h1h_, const bf* h1l_)
{
    const unsigned bufa = sbase + bufoff;
    const int kbase = ch * 64;
    #pragma unroll
    for (int q = 0; q < 4; q++) {          // W: 1024 granules (64 rows x 8 j x 2 planes)
        int idx = tid + q * NTHR;
        int plane = idx >> 9, rem = idx & 511;
        int row = rem >> 3, j = rem & 7;
        const bf* src = (plane ? wl : wh) + (size_t)(sub * 64 + row) * K + kbase + j * 8;
        cp16(bufa + (unsigned)plane * 8192u + SWZ((unsigned)(row * 128 + j * 16)), src);
    }
    #pragma unroll
    for (int q = 0; q < 2; q++) {          // X: 512 granules (32 rows x 8 j x 2 planes)
        int idx = tid + q * NTHR;
        int plane = idx >> 8, rem = idx & 255;
        int row = rem >> 3, j = rem & 7;
        int rg = nb * 32 + row;
        int k = kbase + j * 8;
        const bf* src;
        if (layer == 0)
            src = (k < II) ? (plane ? g_xl : g_xh) + ((size_t)rg * TT + step) * II + k
                           : (plane ? h0l_ : h0h_) + rg * HH + (k - II);
        else
            src = (k < HH) ? (plane ? h0l_ : h0h_) + rg * HH + k
                           : (plane ? h1l_ : h1h_) + rg * HH + (k - HH);
        cp16(bufa + 16384u + (unsigned)plane * 4096u + SWZ((unsigned)(row * 128 + j * 16)), src);
    }
    cp_commit();
}

// ---------------- tensor compute: one k16-step of m32 x n32, 3 bf16 terms -----------
__device__ __forceinline__ void cchunk(
    unsigned bufa, float acc[2][4][4], int wk,
    unsigned aoff, unsigned boff, unsigned bsel, unsigned msk)
{
    const unsigned kb = (((unsigned)wk << 5) | bsel) ^ msk;
    unsigned a0h[4], a1h[4], a0l[4], a1l[4];
    unsigned b0h[4], b1h[4], b0l[4], b1l[4];
    ldsm4(a0h, bufa + aoff + kb);                    // W hi rows 0-15 of m32
    ldsm4(a1h, bufa + aoff + 2048u + kb);            // W hi rows 16-31
    ldsm4(b0h, bufa + 16384u + boff + kb);           // X hi rows 0-15
    ldsm4(b1h, bufa + 16384u + boff + 2048u + kb);   // X hi rows 16-31
    ldsm4(a0l, bufa + 8192u + aoff + kb);            // W lo
    ldsm4(a1l, bufa + 8192u + aoff + 2048u + kb);
    ldsm4(b0l, bufa + 20480u + boff + kb);           // X lo
    ldsm4(b1l, bufa + 20480u + boff + 2048u + kb);

    #pragma unroll
    for (int mi = 0; mi < 2; mi++) {
        const unsigned* ah = mi ? a1h : a0h;
        const unsigned* al = mi ? a1l : a0l;
        // term wh*xh
        mma16816(acc[mi][0], ah, b0h[0], b0h[2]);
        mma16816(acc[mi][1], ah, b0h[1], b0h[3]);
        mma16816(acc[mi][2], ah, b1h[0], b1h[2]);
        mma16816(acc[mi][3], ah, b1h[1], b1h[3]);
        // term wh*xl
        mma16816(acc[mi][0], ah, b0l[0], b0l[2]);
        mma16816(acc[mi][1], ah, b0l[1], b0l[3]);
        mma16816(acc[mi][2], ah, b1l[0], b1l[2]);
        mma16816(acc[mi][3], ah, b1l[1], b1l[3]);
        // term wl*xh
        mma16816(acc[mi][0], al, b0h[0], b0h[2]);
        mma16816(acc[mi][1], al, b0h[1], b0h[3]);
        mma16816(acc[mi][2], al, b1h[0], b1h[2]);
        mma16816(acc[mi][3], al, b1h[1], b1h[3]);
    }
}

// ---------------- main persistent kernel ----------------
__global__ void __launch_bounds__(NTHR, 1) lstm_mma_kernel(
    const float* __restrict__ b_ih0, const float* __restrict__ b_hh0,
    const float* __restrict__ b_ih1, const float* __restrict__ b_hh1,
    const float* __restrict__ h0g, const float* __restrict__ c0g)
{
    extern __shared__ char smem[];
    const unsigned sbase = (unsigned)__cvta_generic_to_shared(smem);
    float* exch = (float*)(smem + SM_EX);           // [4][64][EXPITCH]

    const int tid = threadIdx.x;
    const int lane = tid & 31, wid = tid >> 5;
    const int blk = blockIdx.x;
    const int layer = blk >> 6;            // 0..1
    const int sub = (blk >> 1) & 31;       // gate sub-block (16 h-cols)
    const int nb  = blk & 1;               // batch half
    const int wm = wid & 1;                // m32 tile (0..1)
    const int wk = wid >> 1;               // k16-step (0..3)
    const unsigned finalv = (unsigned)NBLK * (NWAVE + 1);
    const int K = layer ? K1 : K0;
    const int NCH = layer ? NCH1 : NCH0;
    const bf* wh = layer ? g_w1h : g_w0h;
    const bf* wl = layer ? g_w1l : g_w0l;

    // ldmatrix per-lane constants (SW128 swizzle mask from row%8)
    const unsigned msk  = (unsigned)(lane & 7) << 4;
    const unsigned bsel = (unsigned)(lane & 16);
    const unsigned aoff = (unsigned)((32 * wm + (lane & 15)) * 128);
    const unsigned boff = (unsigned)((((lane >> 3) & 1) * 8 + (lane & 7)) * 128);

    // init h planes (each CTA its own 256-elem slice; 128 CTAs cover 32768)
    {
        int i = blk * 256 + tid;
        float v0 = h0g[i];
        bf a = __float2bfloat16(v0);
        g_h0h[0][i] = a; g_h0l[0][i] = __float2bfloat16(v0 - __bfloat162float(a));
        float v1 = h0g[BB * HH + i];
        bf b = __float2bfloat16(v1);
        g_h1h[1][i] = b; g_h1l[1][i] = __float2bfloat16(v1 - __bfloat162float(b));
    }

    // epilogue role: two (h-col, batch) pairs per thread (pairs tid and tid+256)
    float cst[2];
    float bsv[2][4];
    #pragma unroll
    for (int q = 0; q < 2; q++) {
        int pp = tid + q * NTHR;
        int hc = pp & 15, bloc = pp >> 4;
        int colg = sub * 16 + hc;
        cst[q] = c0g[(layer ? BB * HH : 0) + (nb * 32 + bloc) * HH + colg];
        const float* bih = layer ? b_ih1 : b_ih0;
        const float* bhh = layer ? b_hh1 : b_hh0;
        #pragma unroll
        for (int g = 0; g < 4; g++) bsv[q][g] = bih[g * HH + colg] + bhh[g * HH + colg];
    }

    __threadfence();
    __syncthreads();
    if (tid == 0) bar_arrive(&g_ctr, finalv);

    float acc[2][4][4];
    #pragma unroll
    for (int mi = 0; mi < 2; mi++)
        #pragma unroll
        for (int nj = 0; nj < 4; nj++)
            #pragma unroll
            for (int q = 0; q < 4; q++) acc[mi][nj][q] = 0.0f;

    #pragma unroll 1
    for (int s = 0; s < NWAVE; s++) {
        const unsigned wt = (unsigned)(s + 1) * NBLK;
        const bool active = layer ? (s >= 1) : (s < TT);
        if (!active) {
            if (tid == 0) bar_arrive(&g_ctr, finalv);
            continue;
        }
        const int step = layer ? s - 1 : s;
        const int p = s & 1;
        const bf* h0h_ = g_h0h[p]; const bf* h0l_ = g_h0l[p];
        const bf* h1h_ = g_h1h[p]; const bf* h1l_ = g_h1l[p];

        if (layer) {                       // L1: all chunks read prev-wave h
            if (tid == 0) bar_wait(&g_ctr, wt);
            __syncthreads();
        }
        stage(sbase, 0,    0, layer, sub, nb, step, tid, K, wh, wl, h0h_, h0l_, h1h_, h1l_);
        stage(sbase, BUFB, 1, layer, sub, nb, step, tid, K, wh, wl, h0h_, h0l_, h1h_, h1l_);

        #pragma unroll 1
        for (int ch = 0; ch < NCH; ch++) {
            if (ch + 1 < NCH) cp_wait<1>(); else cp_wait<0>();
            __syncthreads();
            if (layer == 0 && ch == 2) {   // before staging chunk 4 (first h chunk)
                if (tid == 0) bar_wait(&g_ctr, wt);
                __syncthreads();
            }
            if (ch + 2 < NCH)
                stage(sbase, (unsigned)((ch + 2) % 3) * BUFB, ch + 2, layer, sub, nb, step, tid,
                      K, wh, wl, h0h_, h0l_, h1h_, h1l_);
            cchunk(sbase + (unsigned)(ch % 3) * BUFB, acc, wk, aoff, boff, bsel, msk);
        }

        // ---- epilogue: regs -> smem exchange (per k-step plane) ----
        {
            const int tq = lane >> 2, tr2 = (lane & 3) * 2;
            float* exb = exch + wk * (64 * EXPITCH);
            #pragma unroll
            for (int mi = 0; mi < 2; mi++) {
                #pragma unroll
                for (int nj = 0; nj < 4; nj++) {
                    int row = 32 * wm + 16 * mi + tq;
                    int col = 8 * nj + tr2;
                    *(float2*)&exb[row * EXPITCH + col] =
                        make_float2(acc[mi][nj][0], acc[mi][nj][1]);
                    *(float2*)&exb[(row + 8) * EXPITCH + col] =
                        make_float2(acc[mi][nj][2], acc[mi][nj][3]);
                    acc[mi][nj][0] = acc[mi][nj][1] = acc[mi][nj][2] = acc[mi][nj][3] = 0.0f;
                }
            }
        }
        __syncthreads();
        {
            bf* ohh = layer ? g_h1h[p ^ 1] : g_h0h[p ^ 1];
            bf* ohl = layer ? g_h1l[p ^ 1] : g_h0l[p ^ 1];
            #pragma unroll
            for (int q = 0; q < 2; q++) {
                int pp = tid + q * NTHR;
                int hc = pp & 15, bloc = pp >> 4;
                int colg = sub * 16 + hc;
                int bglob = nb * 32 + bloc;
                float gi = bsv[q][0], gf = bsv[q][1], gg = bsv[q][2], go = bsv[q][3];
                #pragma unroll
                for (int pl = 0; pl < 4; pl++) {
                    const float* e = exch + pl * (64 * EXPITCH);
                    gi += e[(0  + hc) * EXPITCH + bloc];
                    gf += e[(16 + hc) * EXPITCH + bloc];
                    gg += e[(32 + hc) * EXPITCH + bloc];
                    go += e[(48 + hc) * EXPITCH + bloc];
                }
                float iv = sig_(gi), fv = sig_(gf), gv = tanh_(gg), ov = sig_(go);
                cst[q] = fv * cst[q] + iv * gv;
                float hv = ov * tanh_(cst[q]);
                bf hhv = __float2bfloat16(hv);
                ohh[bglob * HH + colg] = hhv;
                ohl[bglob * HH + colg] = __float2bfloat16(hv - __bfloat162float(hhv));
                if (layer && step == TT - 1) g_h1last[bglob * HH + colg] = hv;
            }
        }
        __threadfence();
        __syncthreads();
        if (tid == 0) bar_arrive(&g_ctr, finalv);
    }
}

// ---------------- prep kernels ----------------
__global__ void prep_w(const float* __restrict__ Wih, const float* __restrict__ Whh,
                       bf* __restrict__ outh, bf* __restrict__ outl, int Kin, int K) {
    long long idx = (long long)blockIdx.x * blockDim.x + threadIdx.x;
    if (idx >= (long long)2048 * K) return;
    int R = (int)(idx / K), k = (int)(idx - (long long)R * K);
    int sub = R >> 6, l = R & 63;
    int g = (l >> 4) * HH + sub * 16 + (l & 15);
    float v = (k < Kin) ? Wih[(size_t)g * Kin + k] : Whh[(size_t)g * HH + (k - Kin)];
    bf hi = __float2bfloat16(v);
    outh[idx] = hi;
    outl[idx] = __float2bfloat16(v - __bfloat162float(hi));
}
__global__ void prep_x(const float* __restrict__ x) {
    long long idx = (long long)blockIdx.x * blockDim.x + threadIdx.x;
    if (idx >= (long long)BB * TT * II) return;
    float v = x[idx];
    bf hi = __float2bfloat16(v);
    g_xh[idx] = hi;
    g_xl[idx] = __float2bfloat16(v - __bfloat162float(hi));
}

// ---------------- final linear head ----------------
__global__ void fc_kernel(const float* __restrict__ W, const float* __restrict__ b,
                          float* __restrict__ out) {
    int w = (blockIdx.x * blockDim.x + threadIdx.x) >> 5;
    int lane = threadIdx.x & 31;
    int r = w >> 7, c = w & 127;
    const float* hr = g_h1last + r * HH + lane * 16;
    const float* wc = W + c * HH + lane * 16;
    float acc = 0.0f;
    #pragma unroll
    for (int k = 0; k < 16; k += 4) {
        float4 hv = *(const float4*)(hr + k);
        float4 wv = *(const float4*)(wc + k);
        acc += hv.x * wv.x + hv.y * wv.y + hv.z * wv.z + hv.w * wv.w;
    }
    #pragma unroll
    for (int off = 16; off; off >>= 1) acc += __shfl_xor_sync(~0u, acc, off);
    if (lane == 0) out[w] = acc + b[c];
}

// ---------------- launch ----------------
extern "C" void kernel_launch(void* const* d_in, const int* in_sizes, int n_in,
                              void* d_out, int out_size) {
    const float* x     = (const float*)d_in[0];
    const float* h0    = (const float*)d_in[1];
    const float* c0    = (const float*)d_in[2];
    const float* W_ih0 = (const float*)d_in[3];
    const float* W_hh0 = (const float*)d_in[4];
    const float* b_ih0 = (const float*)d_in[5];
    const float* b_hh0 = (const float*)d_in[6];
    const float* W_ih1 = (const float*)d_in[7];
    const float* W_hh1 = (const float*)d_in[8];
    const float* b_ih1 = (const float*)d_in[9];
    const float* b_hh1 = (const float*)d_in[10];
    const float* W_fc  = (const float*)d_in[11];
    const float* b_fc  = (const float*)d_in[12];

    bf *w0h, *w0l, *w1h, *w1l;
    cudaGetSymbolAddress((void**)&w0h, g_w0h);
    cudaGetSymbolAddress((void**)&w0l, g_w0l);
    cudaGetSymbolAddress((void**)&w1h, g_w1h);
    cudaGetSymbolAddress((void**)&w1l, g_w1l);

    prep_w<<<(2048 * K0 + 255) / 256, 256>>>(W_ih0, W_hh0, w0h, w0l, II, K0);
    prep_w<<<(2048 * K1 + 255) / 256, 256>>>(W_ih1, W_hh1, w1h, w1l, HH, K1);
    prep_x<<<(BB * TT * II + 255) / 256, 256>>>(x);

    cudaFuncSetAttribute((const void*)lstm_mma_kernel,
                         cudaFuncAttributeMaxDynamicSharedMemorySize, SMEM_TOTAL);
    lstm_mma_kernel<<<NBLK, NTHR, SMEM_TOTAL>>>(b_ih0, b_hh0, b_ih1, b_hh1, h0, c0);

    fc_kernel<<<(BB * CC * 32) / 256, 256>>>(W_fc, b_fc, (float*)d_out);
}

// round 14
// speedup vs baseline: 1.3629x; 1.3629x over previous
#include <cuda_runtime.h>
#include <cuda_fp16.h>
#include <math.h>

typedef __half hf;

#define BB 64
#define TT 512
#define II 256
#define HH 512
#define CC 128

#define NBLK 128
#define NTHR 256
#define NWAVE (TT + 1)   // 513

#define K0 768
#define K1 1024
#define NSC0 6
#define NSC1 8

// smem: 3 superchunk buffers (K=128 = 2 x k64 subtiles), each:
//   [sub0 W 8K][sub1 W 8K][sub0 Xh 4K|Xl 4K][sub1 Xh 4K|Xl 4K] = 32KB
#define BUFB 32768
#define SM_EX (3 * BUFB)
#define EXPITCH 34
#define SMEM_TOTAL (SM_EX + 4 * 64 * EXPITCH * 4)   // 133120

#define SWZ(o) ((o) ^ (((o) >> 3) & 0x70))

// ---------------- device scratch ----------------
__device__ __align__(256) hf g_w0[2048 * K0];
__device__ __align__(256) hf g_w1[2048 * K1];
__device__ __align__(256) hf g_xh[(size_t)BB * TT * II], g_xl[(size_t)BB * TT * II];
__device__ __align__(256) hf g_h0h[8][BB * HH], g_h0l[8][BB * HH];   // 8-deep ring
__device__ __align__(256) hf g_h1h[2][BB * HH], g_h1l[2][BB * HH];
__device__ float g_h1last[BB * HH];
__device__ unsigned g_ctr0, g_ctr1, g_done;   // zero-init; reset at kernel end

// ---------------- primitives ----------------
__device__ __forceinline__ void cp16(unsigned saddr, const void* g) {
    asm volatile("cp.async.cg.shared.global [%0], [%1], 16;\n" :: "r"(saddr), "l"(g) : "memory");
}
__device__ __forceinline__ void cp_commit() {
    asm volatile("cp.async.commit_group;\n" ::: "memory");
}
template <int N> __device__ __forceinline__ void cp_wait() {
    asm volatile("cp.async.wait_group %0;\n" :: "n"(N) : "memory");
}
__device__ __forceinline__ void bar_arrive(unsigned* ctr) {
    unsigned old;
    asm volatile("atom.release.gpu.global.add.u32 %0, [%1], %2;"
                 : "=r"(old) : "l"(ctr), "r"(1u) : "memory");
}
__device__ __forceinline__ void bar_wait(unsigned* ctr, unsigned target) {
    unsigned v;
    do {
        asm volatile("ld.acquire.gpu.global.u32 %0, [%1];" : "=r"(v) : "l"(ctr) : "memory");
    } while (v < target);
}
__device__ __forceinline__ float sig_(float x)  { return 1.0f / (1.0f + __expf(-x)); }
__device__ __forceinline__ float tanh_(float x) { return 2.0f / (1.0f + __expf(-2.0f * x)) - 1.0f; }

__device__ __forceinline__ void ldsm4(unsigned* r, unsigned addr) {
    asm volatile("ldmatrix.sync.aligned.m8n8.x4.shared.b16 {%0,%1,%2,%3}, [%4];"
                 : "=r"(r[0]), "=r"(r[1]), "=r"(r[2]), "=r"(r[3]) : "r"(addr));
}
__device__ __forceinline__ void mma16816(float* c, const unsigned* a, unsigned b0, unsigned b1) {
    asm volatile(
        "mma.sync.aligned.m16n8k16.row.col.f32.f16.f16.f32 "
        "{%0,%1,%2,%3}, {%4,%5,%6,%7}, {%8,%9}, {%0,%1,%2,%3};"
        : "+f"(c[0]), "+f"(c[1]), "+f"(c[2]), "+f"(c[3])
        : "r"(a[0]), "r"(a[1]), "r"(a[2]), "r"(a[3]), "r"(b0), "r"(b1));
}

// ---------------- staging: one K=128 superchunk (2 k64 subtiles) ----------------
__device__ __forceinline__ void stage(
    unsigned bufa, int sc, int layer, int sub, int nb, int step, int tid, int K,
    const hf* __restrict__ w,
    const hf* h0h_, const hf* h0l_, const hf* h1h_, const hf* h1l_)
{
    #pragma unroll
    for (int t = 0; t < 2; t++) {
        const int kb = sc * 128 + t * 64;
        #pragma unroll
        for (int q = 0; q < 2; q++) {           // W: 512 granules per subtile (hi only)
            int idx = tid + q * NTHR;
            int row = idx >> 3, j = idx & 7;
            const hf* src = w + (size_t)(sub * 64 + row) * K + kb + j * 8;
            cp16(bufa + (unsigned)t * 8192u + SWZ((unsigned)(row * 128 + j * 16)), src);
        }
        #pragma unroll
        for (int q = 0; q < 2; q++) {           // X: 512 granules per subtile (hi+lo)
            int idx = tid + q * NTHR;
            int plane = idx >> 8, rem = idx & 255;
            int row = rem >> 3, j = rem & 7;
            int rg = nb * 32 + row;
            int k = kb + j * 8;
            const hf* src;
            if (layer == 0)
                src = (k < II) ? (plane ? g_xl : g_xh) + ((size_t)rg * TT + step) * II + k
                               : (plane ? h0l_ : h0h_) + rg * HH + (k - II);
            else
                src = (k < HH) ? (plane ? h0l_ : h0h_) + rg * HH + k
                               : (plane ? h1l_ : h1h_) + rg * HH + (k - HH);
            cp16(bufa + 16384u + (unsigned)t * 8192u + (unsigned)plane * 4096u
                 + SWZ((unsigned)(row * 128 + j * 16)), src);
        }
    }
    cp_commit();
}

// ---------------- tensor compute: superchunk, m32 x n32, 2 fp16 terms ----------------
__device__ __forceinline__ void cchunk(
    unsigned bufa, float acc[2][4][4], unsigned kb, unsigned aoff, unsigned boff)
{
    #pragma unroll
    for (int t = 0; t < 2; t++) {
        const unsigned wb = bufa + (unsigned)t * 8192u;
        const unsigned xb = bufa + 16384u + (unsigned)t * 8192u;
        unsigned a0[4], a1[4], b0h[4], b1h[4], b0l[4], b1l[4];
        ldsm4(a0, wb + aoff + kb);
        ldsm4(a1, wb + aoff + 2048u + kb);
        ldsm4(b0h, xb + boff + kb);
        ldsm4(b1h, xb + boff + 2048u + kb);
        ldsm4(b0l, xb + 4096u + boff + kb);
        ldsm4(b1l, xb + 4096u + boff + 2048u + kb);
        #pragma unroll
        for (int mi = 0; mi < 2; mi++) {
            const unsigned* a = mi ? a1 : a0;
            mma16816(acc[mi][0], a, b0h[0], b0h[2]);
            mma16816(acc[mi][1], a, b0h[1], b0h[3]);
            mma16816(acc[mi][2], a, b1h[0], b1h[2]);
            mma16816(acc[mi][3], a, b1h[1], b1h[3]);
            mma16816(acc[mi][0], a, b0l[0], b0l[2]);
            mma16816(acc[mi][1], a, b0l[1], b0l[3]);
            mma16816(acc[mi][2], a, b1l[0], b1l[2]);
            mma16816(acc[mi][3], a, b1l[1], b1l[3]);
        }
    }
}

// ---------------- main persistent kernel ----------------
__global__ void __launch_bounds__(NTHR, 1) lstm_mma_kernel(
    const float* __restrict__ b_ih0, const float* __restrict__ b_hh0,
    const float* __restrict__ b_ih1, const float* __restrict__ b_hh1,
    const float* __restrict__ h0g, const float* __restrict__ c0g)
{
    extern __shared__ char smem[];
    const unsigned sbase = (unsigned)__cvta_generic_to_shared(smem);
    float* exch = (float*)(smem + SM_EX);           // [4][64][EXPITCH]

    const int tid = threadIdx.x;
    const int lane = tid & 31, wid = tid >> 5;
    const int blk = blockIdx.x;
    const int layer = blk >> 6;            // 0..1
    const int sub = (blk >> 1) & 31;       // gate sub-block (16 h-cols)
    const int nb  = blk & 1;               // batch half
    const int wm = wid & 1;                // m32 tile
    const int wk = wid >> 1;               // k16-step within k64 subtile (0..3)
    const int K = layer ? K1 : K0;
    const int NSC = layer ? NSC1 : NSC0;
    const hf* w = layer ? g_w1 : g_w0;
    unsigned* ctrOwn   = layer ? &g_ctr1 : &g_ctr0;

    // ldmatrix per-lane constants (SW128 swizzle mask from row%8)
    const unsigned msk  = (unsigned)(lane & 7) << 4;
    const unsigned bsel = (unsigned)(lane & 16);
    const unsigned kb   = (((unsigned)wk << 5) | bsel) ^ msk;
    const unsigned aoff = (unsigned)((32 * wm + (lane & 15)) * 128);
    const unsigned boff = (unsigned)((((lane >> 3) & 1) * 8 + (lane & 7)) * 128);

    // init: h0 initial -> ring slot 7 ("h0(-1)"), h1 initial -> slot 0
    {
        int i = blk * 256 + tid;
        float v0 = h0g[i];
        hf a = __float2half(v0);
        g_h0h[7][i] = a; g_h0l[7][i] = __float2half(v0 - __half2float(a));
        float v1 = h0g[BB * HH + i];
        hf b = __float2half(v1);
        g_h1h[0][i] = b; g_h1l[0][i] = __float2half(v1 - __half2float(b));
    }

    // epilogue role: two (h-col, batch) pairs per thread
    float cst[2];
    float bsv[2][4];
    #pragma unroll
    for (int q = 0; q < 2; q++) {
        int pp = tid + q * NTHR;
        int hc = pp & 15, bloc = pp >> 4;
        int colg = sub * 16 + hc;
        cst[q] = c0g[(layer ? BB * HH : 0) + (nb * 32 + bloc) * HH + colg];
        const float* bih = layer ? b_ih1 : b_ih0;
        const float* bhh = layer ? b_hh1 : b_hh0;
        #pragma unroll
        for (int g = 0; g < 4; g++) bsv[q][g] = bih[g * HH + colg] + bhh[g * HH + colg];
    }

    __threadfence();
    __syncthreads();
    if (tid == 0) bar_arrive(ctrOwn);      // init publish

    float acc[2][4][4];
    #pragma unroll
    for (int mi = 0; mi < 2; mi++)
        #pragma unroll
        for (int nj = 0; nj < 4; nj++)
            #pragma unroll
            for (int q = 0; q < 4; q++) acc[mi][nj][q] = 0.0f;

    #pragma unroll 1
    for (int s = 0; s < NWAVE; s++) {
        const bool active = layer ? (s >= 1) : (s < TT);
        if (!active) {
            if (tid == 0) bar_arrive(ctrOwn);
            continue;
        }
        const int step = layer ? s - 1 : s;
        const unsigned wt = 64u * (unsigned)(s + 1);
        const hf* h0h_ = g_h0h[(s + 7) & 7];     // h0(s-1)
        const hf* h0l_ = g_h0l[(s + 7) & 7];
        const hf* h1h_ = g_h1h[(s + 1) & 1];     // h1(step-1)
        const hf* h1l_ = g_h1l[(s + 1) & 1];

        if (layer) {
            // h0(s-1) needed from superchunk 0: L0 runs ahead, usually satisfied
            if (tid == 0) bar_wait(&g_ctr0, wt);
            __syncthreads();
        } else if (s >= 7) {
            // ring safety: h0(s) write clobbers h0(s-8); L1 must be done wave s-7
            if (tid == 0) bar_wait(&g_ctr1, 64u * (unsigned)(s - 5));
            __syncthreads();
        }

        stage(sbase + 0 * BUFB, 0, layer, sub, nb, step, tid, K, w, h0h_, h0l_, h1h_, h1l_);
        stage(sbase + 1 * BUFB, 1, layer, sub, nb, step, tid, K, w, h0h_, h0l_, h1h_, h1l_);

        #pragma unroll 1
        for (int sc = 0; sc < NSC; sc++) {
            if (sc + 1 < NSC) cp_wait<1>(); else cp_wait<0>();
            // gates before staging the first h-dependent superchunk
            if (layer == 0 && sc == 0) {          // stage(2) reads h0(s-1)
                if (tid == 0) bar_wait(&g_ctr0, wt);
            }
            if (layer == 1 && sc == 2) {          // stage(4) reads h1(step-1)
                if (tid == 0) bar_wait(&g_ctr1, wt);
            }
            __syncthreads();
            if (sc + 2 < NSC)
                stage(sbase + (unsigned)((sc + 2) % 3) * BUFB, sc + 2, layer, sub, nb, step,
                      tid, K, w, h0h_, h0l_, h1h_, h1l_);
            cchunk(sbase + (unsigned)(sc % 3) * BUFB, acc, kb, aoff, boff);
        }

        // ---- epilogue: regs -> smem exchange (per k16-plane) ----
        {
            const int tq = lane >> 2, tr2 = (lane & 3) * 2;
            float* exb = exch + wk * (64 * EXPITCH);
            #pragma unroll
            for (int mi = 0; mi < 2; mi++) {
                #pragma unroll
                for (int nj = 0; nj < 4; nj++) {
                    int row = 32 * wm + 16 * mi + tq;
                    int col = 8 * nj + tr2;
                    *(float2*)&exb[row * EXPITCH + col] =
                        make_float2(acc[mi][nj][0], acc[mi][nj][1]);
                    *(float2*)&exb[(row + 8) * EXPITCH + col] =
                        make_float2(acc[mi][nj][2], acc[mi][nj][3]);
                    acc[mi][nj][0] = acc[mi][nj][1] = acc[mi][nj][2] = acc[mi][nj][3] = 0.0f;
                }
            }
        }
        __syncthreads();
        {
            hf* ohh = layer ? g_h1h[s & 1] : g_h0h[s & 7];
            hf* ohl = layer ? g_h1l[s & 1] : g_h0l[s & 7];
            #pragma unroll
            for (int q = 0; q < 2; q++) {
                int pp = tid + q * NTHR;
                int hc = pp & 15, bloc = pp >> 4;
                int colg = sub * 16 + hc;
                int bglob = nb * 32 + bloc;
                float gi = bsv[q][0], gf = bsv[q][1], gg = bsv[q][2], go = bsv[q][3];
                #pragma unroll
                for (int pl = 0; pl < 4; pl++) {
                    const float* e = exch + pl * (64 * EXPITCH);
                    gi += e[(0  + hc) * EXPITCH + bloc];
                    gf += e[(16 + hc) * EXPITCH + bloc];
                    gg += e[(32 + hc) * EXPITCH + bloc];
                    go += e[(48 + hc) * EXPITCH + bloc];
                }
                float iv = sig_(gi), fv = sig_(gf), gv = tanh_(gg), ov = sig_(go);
                cst[q] = fv * cst[q] + iv * gv;
                float hv = ov * tanh_(cst[q]);
                hf hhv = __float2half(hv);
                ohh[bglob * HH + colg] = hhv;
                ohl[bglob * HH + colg] = __float2half(hv - __half2float(hhv));
                if (layer && step == TT - 1) g_h1last[bglob * HH + colg] = hv;
            }
        }
        __threadfence();
        __syncthreads();
        if (tid == 0) bar_arrive(ctrOwn);
    }

    // completion: last CTA overall resets counters for graph replay
    __syncthreads();
    if (tid == 0) {
        unsigned old;
        asm volatile("atom.release.gpu.global.add.u32 %0, [%1], %2;"
                     : "=r"(old) : "l"(&g_done), "r"(1u) : "memory");
        if (old == NBLK - 1) {
            asm volatile("st.relaxed.gpu.global.u32 [%0], %1;" :: "l"(&g_ctr0), "r"(0u) : "memory");
            asm volatile("st.relaxed.gpu.global.u32 [%0], %1;" :: "l"(&g_ctr1), "r"(0u) : "memory");
            asm volatile("st.relaxed.gpu.global.u32 [%0], %1;" :: "l"(&g_done), "r"(0u) : "memory");
        }
    }
}

// ---------------- prep kernels ----------------
__global__ void prep_w(const float* __restrict__ Wih, const float* __restrict__ Whh,
                       hf* __restrict__ outp, int Kin, int K) {
    long long idx = (long long)blockIdx.x * blockDim.x + threadIdx.x;
    if (idx >= (long long)2048 * K) return;
    int R = (int)(idx / K), k = (int)(idx - (long long)R * K);
    int sub = R >> 6, l = R & 63;
    int g = (l >> 4) * HH + sub * 16 + (l & 15);
    float v = (k < Kin) ? Wih[(size_t)g * Kin + k] : Whh[(size_t)g * HH + (k - Kin)];
    outp[idx] = __float2half(v);
}
__global__ void prep_x(const float* __restrict__ x) {
    long long idx = (long long)blockIdx.x * blockDim.x + threadIdx.x;
    if (idx >= (long long)BB * TT * II) return;
    float v = x[idx];
    hf hi = __float2half(v);
    g_xh[idx] = hi;
    g_xl[idx] = __float2half(v - __half2float(hi));
}

// ---------------- final linear head ----------------
__global__ void fc_kernel(const float* __restrict__ W, const float* __restrict__ b,
                          float* __restrict__ out) {
    int w = (blockIdx.x * blockDim.x + threadIdx.x) >> 5;
    int lane = threadIdx.x & 31;
    int r = w >> 7, c = w & 127;
    const float* hr = g_h1last + r * HH + lane * 16;
    const float* wc = W + c * HH + lane * 16;
    float acc = 0.0f;
    #pragma unroll
    for (int k = 0; k < 16; k += 4) {
        float4 hv = *(const float4*)(hr + k);
        float4 wv = *(const float4*)(wc + k);
        acc += hv.x * wv.x + hv.y * wv.y + hv.z * wv.z + hv.w * wv.w;
    }
    #pragma unroll
    for (int off = 16; off; off >>= 1) acc += __shfl_xor_sync(~0u, acc, off);
    if (lane == 0) out[w] = acc + b[c];
}

// ---------------- launch ----------------
extern "C" void kernel_launch(void* const* d_in, const int* in_sizes, int n_in,
                              void* d_out, int out_size) {
    const float* x     = (const float*)d_in[0];
    const float* h0    = (const float*)d_in[1];
    const float* c0    = (const float*)d_in[2];
    const float* W_ih0 = (const float*)d_in[3];
    const float* W_hh0 = (const float*)d_in[4];
    const float* b_ih0 = (const float*)d_in[5];
    const float* b_hh0 = (const float*)d_in[6];
    const float* W_ih1 = (const float*)d_in[7];
    const float* W_hh1 = (const float*)d_in[8];
    const float* b_ih1 = (const float*)d_in[9];
    const float* b_hh1 = (const float*)d_in[10];
    const float* W_fc  = (const float*)d_in[11];
    const float* b_fc  = (const float*)d_in[12];

    hf *w0, *w1;
    cudaGetSymbolAddress((void**)&w0, g_w0);
    cudaGetSymbolAddress((void**)&w1, g_w1);

    prep_w<<<(2048 * K0 + 255) / 256, 256>>>(W_ih0, W_hh0, w0, II, K0);
    prep_w<<<(2048 * K1 + 255) / 256, 256>>>(W_ih1, W_hh1, w1, HH, K1);
    prep_x<<<(BB * TT * II + 255) / 256, 256>>>(x);

    cudaFuncSetAttribute((const void*)lstm_mma_kernel,
                         cudaFuncAttributeMaxDynamicSharedMemorySize, SMEM_TOTAL);
    lstm_mma_kernel<<<NBLK, NTHR, SMEM_TOTAL>>>(b_ih0, b_hh0, b_ih1, b_hh1, h0, c0);

    fc_kernel<<<(BB * CC * 32) / 256, 256>>>(W_fc, b_fc, (float*)d_out);
}